// round 16
// baseline (speedup 1.0000x reference)
#include <cuda_runtime.h>
#include <cuda_fp16.h>
#include <math.h>
#include <stdint.h>

// ===========================================================================
// ScoreMagnitudeMetric via warp-level mma.sync fp16 single-term GEMM:
//   scores = x @ W  ~=  fp16(x) @ fp16(W^T)   (fp32 accumulation)
//   n2[b] = ||scores_b||^2 ; out[b] = (alpha*n2^2 + beta) * ||x_dot_b||^2
// R16: R15 base + filler polish: __ldcs streaming loads for x_dot (keeps xh
// L2-resident for y-slices 1..7) and 2-row-interleaved accumulation (2x MLP,
// less filler SM-slot time). Per-row summation order unchanged.
// ===========================================================================

#define MAXB 32768
#define MAXP 2048
#define MAXD 1024

#define BM 256
#define BN 128
#define BK 64
#define NSLICE_MAX (MAXD / BN)   // 8

// scratch (device globals; no allocation allowed)
__device__ __half g_xh[(size_t)MAXB * MAXD];
__device__ __half g_ph[(size_t)MAXP * MAXD];
__device__ __half g_wh[(size_t)MAXD * MAXD];   // fp16(W^T)
__device__ float g_xparts[NSLICE_MAX * MAXB];
__device__ float g_pparts[NSLICE_MAX * MAXP];
__device__ float g_d2[MAXB];
__device__ int   g_cal[2];                     // [0]=max(n4) bits, [1]=min(n4) bits

// ---------------------------------------------------------------------------
// helpers
// ---------------------------------------------------------------------------
__device__ __forceinline__ uint32_t smem_to_u32(const void* p) {
    uint32_t a;
    asm("{ .reg .u64 t; cvta.to.shared.u64 t, %1; cvt.u32.u64 %0, t; }"
        : "=r"(a) : "l"(p));
    return a;
}

#define CP_ASYNC16(sm, g) \
    asm volatile("cp.async.cg.shared.global [%0], [%1], 16;" :: "r"(sm), "l"(g) : "memory")

// deferred arrival on mbar when all prior cp.async of this thread complete
#define CP_MBAR_ARRIVE(mbar) \
    asm volatile("cp.async.mbarrier.arrive.noinc.shared.b64 [%0];" \
                 :: "r"((uint32_t)(mbar)) : "memory")

#define MBARRIER_INIT(addr, cnt) \
    asm volatile("mbarrier.init.shared.b64 [%0], %1;" \
                 :: "r"((uint32_t)(addr)), "r"((uint32_t)(cnt)) : "memory")

#define MBARRIER_ARRIVE(addr) \
    asm volatile("mbarrier.arrive.shared.b64 _, [%0];" \
                 :: "r"((uint32_t)(addr)) : "memory")

#define MBARRIER_WAIT_PARITY(addr, par) do {                                   \
    uint32_t _m = (uint32_t)(addr); uint32_t _p = (uint32_t)(par); uint32_t _d;\
    asm volatile("{\n\t.reg .pred p;\n\t"                                      \
        "mbarrier.try_wait.parity.acquire.cta.shared::cta.b64 p, [%1], %2;\n\t"\
        "selp.b32 %0, 1, 0, p;\n\t}" : "=r"(_d) : "r"(_m), "r"(_p) : "memory");\
    if (!_d) {                                                                 \
        asm volatile("{\n\t.reg .pred P1;\n\t"                                 \
            "WL_%=:\n\t"                                                       \
            "mbarrier.try_wait.parity.acquire.cta.shared::cta.b64 P1, [%0], %1, 0x989680;\n\t" \
            "@P1 bra.uni WD_%=;\n\t"                                           \
            "bra.uni WL_%=;\n\t"                                               \
            "WD_%=:\n\t}" :: "r"(_m), "r"(_p) : "memory");                     \
    }                                                                          \
} while (0)

__device__ __forceinline__ void ldsm_x4(uint32_t* r, uint32_t addr) {
    asm volatile("ldmatrix.sync.aligned.m8n8.x4.shared.b16 {%0,%1,%2,%3}, [%4];"
                 : "=r"(r[0]), "=r"(r[1]), "=r"(r[2]), "=r"(r[3]) : "r"(addr));
}

__device__ __forceinline__ void mma16816(float* c, const uint32_t* a,
                                         uint32_t b0, uint32_t b1) {
    asm volatile(
        "mma.sync.aligned.m16n8k16.row.col.f32.f16.f16.f32 "
        "{%0,%1,%2,%3}, {%4,%5,%6,%7}, {%8,%9}, {%0,%1,%2,%3};"
        : "+f"(c[0]), "+f"(c[1]), "+f"(c[2]), "+f"(c[3])
        : "r"(a[0]), "r"(a[1]), "r"(a[2]), "r"(a[3]), "r"(b0), "r"(b1));
}

// ---------------------------------------------------------------------------
// Unified prep: grid sections on blockIdx.x
//   [0, nWb)       : W [k][j] -> Wt [j][k] fp16 (32x32 transpose tiles)
//   [nWb, ...)     : fp32 -> fp16 convert of x then pos (float4 lanes)
// Block 0 / thread 0 also re-initializes the calibration atomic cells.
// ---------------------------------------------------------------------------
__global__ __launch_bounds__(256)
void prep_kernel(const float* __restrict__ W, __half* __restrict__ wth, int D,
                 int nWb,
                 const float* __restrict__ x, __half* __restrict__ xh, int nx4,
                 const float* __restrict__ p, __half* __restrict__ ph, int np4)
{
    const int tid = threadIdx.x;
    const int bx  = blockIdx.x;

    if (bx < nWb) {
        if (bx == 0 && tid == 0) {
            g_cal[0] = 0;            // bits of 0.0f     (running max, n4 > 0)
            g_cal[1] = 0x7F7FFFFF;   // bits of FLT_MAX  (running min)
        }
        __shared__ float t[32][33];
        const int nJ = D / 32;
        const int j0 = (bx % nJ) * 32, k0 = (bx / nJ) * 32;
        const int tx = tid & 31, ty = tid >> 5;   // 32 x 8
        #pragma unroll
        for (int r = 0; r < 4; ++r)
            t[ty + 8 * r][tx] = W[(size_t)(k0 + ty + 8 * r) * D + j0 + tx];
        __syncthreads();
        #pragma unroll
        for (int r = 0; r < 4; ++r) {
            float v = t[tx][ty + 8 * r];
            wth[(size_t)(j0 + ty + 8 * r) * D + k0 + tx] = __float2half_rn(v);
        }
        return;
    }

    int i = (bx - nWb) * 256 + tid;
    const float* src;
    __half* dst;
    if (i < nx4) { src = x; dst = xh; }
    else         { src = p; dst = ph; i -= nx4; if (i >= np4) return; }
    float4 v = reinterpret_cast<const float4*>(src)[i];
    __half2* hp = reinterpret_cast<__half2*>(dst) + 2 * i;
    hp[0] = __half2(__float2half_rn(v.x), __float2half_rn(v.y));
    hp[1] = __half2(__float2half_rn(v.z), __float2half_rn(v.w));
}

// ---------------------------------------------------------------------------
// mma.sync GEMM-norm + fused x_dot row-norms. Grid sections on blockIdx.x:
//   [0, nxB)            : 256-row tiles of X  -> xparts
//   [nxB, nxB+npB)      : 256-row tiles of Pm -> pparts
//   [nxB+npB, +ndB)     : x_dot row sum-of-squares -> d2
//                         (each (fb, y) block handles a distinct 32-row strip;
//                          __ldcs streaming loads; 2 rows in flight per warp)
// GEMM block: 256 rows x 128 cols, 8 warps (4x2 of 64x64), 256 threads,
// 1 CTA/SM.  K in 64-chunks, 3-stage cp.async pipeline via mbarriers:
// FULL[s] (256 cp.async arrivals), CONS[s] (8 per-warp elected arrivals).
// Smem tile rows: 64 halves = 128 B data, 144 B stride (conflict-free ldsm).
// ---------------------------------------------------------------------------
#define A_TILE_B (256 * 144)                // 36864
#define B_TILE_B (128 * 144)                // 18432
#define A_OFF    0
#define B_OFF    (A_TILE_B)
#define STAGE_B  (A_TILE_B + B_TILE_B)      // 55296
#define NSTAGE   3
#define MBAR_OFF (NSTAGE * STAGE_B)         // 165888
#define SMEM_TOTAL (MBAR_OFF + 64)          // 165952

__global__ __launch_bounds__(256, 1)
void mma_gemm_norm(const __half* __restrict__ X,
                   const __half* __restrict__ Pm,
                   const __half* __restrict__ Wm,
                   const float* __restrict__ x_dot,
                   int D, int nxB, int npB,
                   float* __restrict__ xparts, int Brows,
                   float* __restrict__ pparts, int Prows,
                   float* __restrict__ d2)
{
    extern __shared__ __align__(128) char smem[];
    const uint32_t sm0 = smem_to_u32(smem);

    const int tid  = threadIdx.x;
    const int wid  = tid >> 5;
    const int lane = tid & 31;

    // ---- section 3: x_dot row-norms (DRAM-bound filler blocks) ----------
    // Each (fb, y) handles 32 rows: base = fb*256 + y*32; 4 rows per warp,
    // processed 2-at-a-time (independent accumulator streams -> 2x MLP).
    // __ldcs: evict-first so x_dot streaming doesn't evict xh from L2.
    if ((int)blockIdx.x >= nxB + npB) {
        const int fb = (int)blockIdx.x - nxB - npB;
        const int base = fb * 256 + (int)blockIdx.y * 32 + wid * 4;
        const int D4 = D >> 2;
        #pragma unroll
        for (int rp = 0; rp < 4; rp += 2) {
            const float4* xd0 = reinterpret_cast<const float4*>(x_dot)
                              + (size_t)(base + rp) * D4;
            const float4* xd1 = reinterpret_cast<const float4*>(x_dot)
                              + (size_t)(base + rp + 1) * D4;
            float s0 = 0.f, s1 = 0.f;
            for (int i = lane; i < D4; i += 32) {
                float4 v0 = __ldcs(&xd0[i]);
                float4 v1 = __ldcs(&xd1[i]);
                s0 += v0.x * v0.x + v0.y * v0.y + v0.z * v0.z + v0.w * v0.w;
                s1 += v1.x * v1.x + v1.y * v1.y + v1.z * v1.z + v1.w * v1.w;
            }
            #pragma unroll
            for (int off = 16; off > 0; off >>= 1) {
                s0 += __shfl_down_sync(0xFFFFFFFFu, s0, off);
                s1 += __shfl_down_sync(0xFFFFFFFFu, s1, off);
            }
            if (lane == 0) {
                d2[base + rp]     = s0;
                d2[base + rp + 1] = s1;
            }
        }
        return;
    }

    // ---- sections 1+2: GEMM-norm ----------------------------------------
    const int wm   = wid >> 1;          // 0..3 -> rows wm*64
    const int wn   = wid & 1;           // 0..1 -> cols wn*64
    const int KC   = D / BK;            // 16

    const bool isX = ((int)blockIdx.x < nxB);
    const int  mb  = isX ? (int)blockIdx.x : (int)blockIdx.x - nxB;
    const int  m0  = mb * BM;
    const int  n0  = blockIdx.y * BN;
    float* parts   = isX ? xparts : pparts;
    const int rowStride = isX ? Brows : Prows;

    const __half* gA = (isX ? X : Pm) + (size_t)m0 * D;
    const __half* gB = Wm + (size_t)n0 * D;

    const uint32_t FULL = sm0 + MBAR_OFF;        // 3 x 8B
    const uint32_t CONS = sm0 + MBAR_OFF + 24;   // 3 x 8B

    if (tid == 0) {
        #pragma unroll
        for (int s = 0; s < NSTAGE; ++s) {
            MBARRIER_INIT(FULL + 8 * s, 256);   // all threads' cp.async groups
            MBARRIER_INIT(CONS + 8 * s, 8);     // one elected lane per warp
        }
    }
    __syncthreads();

    float acc[4][8][4];
    #pragma unroll
    for (int i = 0; i < 4; ++i)
        #pragma unroll
        for (int j = 0; j < 8; ++j)
            #pragma unroll
            for (int c = 0; c < 4; ++c) acc[i][j][c] = 0.f;

    auto load_chunk = [&](int kc, int s) {
        const uint32_t sb = sm0 + (uint32_t)s * STAGE_B;
        const int kb = kc * BK;          // halves
        // A: 256 rows x 8 16B-segments = 2048 units; 8 per thread
        #pragma unroll
        for (int i = 0; i < 8; ++i) {
            int idx = tid + 256 * i;     // 0..2047
            int r = idx >> 3, c = idx & 7;
            uint32_t so = (uint32_t)(r * 144 + c * 16);
            CP_ASYNC16(sb + A_OFF + so, gA + (size_t)r * D + kb + c * 8);
        }
        // B: 128 rows x 8 segments = 1024 units; 4 per thread
        #pragma unroll
        for (int i = 0; i < 4; ++i) {
            int idx = tid + 256 * i;     // 0..1023
            int r = idx >> 3, c = idx & 7;
            uint32_t so = (uint32_t)(r * 144 + c * 16);
            CP_ASYNC16(sb + B_OFF + so, gB + (size_t)r * D + kb + c * 8);
        }
    };

    // ldmatrix per-lane address pieces (within-warp), hoisted
    const int a_row = (lane & 15);
    const int a_ku  = (lane >> 4);
    const int b_row = ((lane >> 4) << 3) + (lane & 7);
    const int b_ku  = ((lane >> 3) & 1);
    const int mrow  = wm * 64;
    const int nrow  = wn * 64;
    const uint32_t aBase0 = (uint32_t)((mrow + a_row) * 144 + a_ku * 16);
    const uint32_t bBase0 = (uint32_t)((nrow + b_row) * 144 + b_ku * 16);

    // prologue: chunks 0 and 1 in flight (deferred arrivals on FULL)
    load_chunk(0, 0);
    CP_MBAR_ARRIVE(FULL + 0);
    load_chunk(1, 1);
    CP_MBAR_ARRIVE(FULL + 8);

    for (int kc = 0; kc < KC; ++kc) {
        const int s = kc % NSTAGE;

        // produce chunk kc+2 into stage (kc+2)%3 (wait its previous reader)
        if (kc + 2 < KC) {
            const int s2 = (kc + 2) % NSTAGE;
            const uint32_t pc = (kc == 0) ? 1u : (uint32_t)(((kc - 1) / 3) & 1);
            MBARRIER_WAIT_PARITY(CONS + 8 * s2, pc);
            load_chunk(kc + 2, s2);
            CP_MBAR_ARRIVE(FULL + 8 * s2);
        }

        // consume chunk kc
        MBARRIER_WAIT_PARITY(FULL + 8 * s, (uint32_t)((kc / 3) & 1));

        const uint32_t sb = sm0 + (uint32_t)s * STAGE_B;
        const uint32_t aB = sb + A_OFF + aBase0;
        const uint32_t bB = sb + B_OFF + bBase0;
        #pragma unroll
        for (int ks = 0; ks < 4; ++ks) {        // four k16 steps per chunk
            const uint32_t kOff = (uint32_t)(ks * 32);
            uint32_t ah[4][4], bh[4][4];
            #pragma unroll
            for (int mt = 0; mt < 4; ++mt)
                ldsm_x4(ah[mt], aB + kOff + (uint32_t)(mt * 16 * 144));
            #pragma unroll
            for (int ng = 0; ng < 4; ++ng)
                ldsm_x4(bh[ng], bB + kOff + (uint32_t)(ng * 16 * 144));
            #pragma unroll
            for (int mt = 0; mt < 4; ++mt) {
                #pragma unroll
                for (int nt = 0; nt < 8; ++nt) {
                    uint32_t b0 = bh[nt >> 1][2 * (nt & 1)];
                    uint32_t b1 = bh[nt >> 1][2 * (nt & 1) + 1];
                    mma16816(acc[mt][nt], ah[mt], b0, b1);
                }
            }
        }

        // warp done reading stage s: one elected arrival per warp.
        if (lane == 0) MBARRIER_ARRIVE(CONS + 8 * s);
    }
    __syncthreads();   // all warps done (and all loads consumed) before reuse

    // ---- epilogue: row-wise sum of squares -------------------------------
    float* rbuf = reinterpret_cast<float*>(smem);   // [256][2]
    float rs0[4], rs1[4];
    #pragma unroll
    for (int mt = 0; mt < 4; ++mt) {
        float s0 = 0.f, s1 = 0.f;
        #pragma unroll
        for (int nt = 0; nt < 8; ++nt) {
            s0 += acc[mt][nt][0] * acc[mt][nt][0] + acc[mt][nt][1] * acc[mt][nt][1];
            s1 += acc[mt][nt][2] * acc[mt][nt][2] + acc[mt][nt][3] * acc[mt][nt][3];
        }
        s0 += __shfl_xor_sync(0xFFFFFFFFu, s0, 1);
        s0 += __shfl_xor_sync(0xFFFFFFFFu, s0, 2);
        s1 += __shfl_xor_sync(0xFFFFFFFFu, s1, 1);
        s1 += __shfl_xor_sync(0xFFFFFFFFu, s1, 2);
        rs0[mt] = s0;
        rs1[mt] = s1;
    }
    if ((lane & 3) == 0) {
        int rq = lane >> 2;
        #pragma unroll
        for (int mt = 0; mt < 4; ++mt) {
            int row = mrow + mt * 16 + rq;
            rbuf[row * 2 + wn] = rs0[mt];
            rbuf[(row + 8) * 2 + wn] = rs1[mt];
        }
    }
    __syncthreads();
    if (tid < BM) {
        float tot = rbuf[tid * 2 + 0] + rbuf[tid * 2 + 1];
        parts[(size_t)blockIdx.y * rowStride + m0 + tid] = tot;
    }
}

// ---------------------------------------------------------------------------
// Calibration: per-row n2 -> n4; block-reduce max/min; ONE atomicMax/Min per
// block on int-punned positive floats (deterministic).
// ---------------------------------------------------------------------------
__global__ __launch_bounds__(256)
void calib2_kernel(const float* __restrict__ pparts, int P, int nparts,
                   int* __restrict__ cal)
{
    __shared__ float smx[256], smn[256];
    const int tid = threadIdx.x;
    const int r = blockIdx.x * 256 + tid;

    float n4;
    {
        float n2 = 0.f;
        for (int y = 0; y < nparts; ++y) n2 += pparts[(size_t)y * P + r];
        n4 = n2 * n2;
    }
    smx[tid] = n4;
    smn[tid] = n4;
    __syncthreads();
    for (int s = 128; s > 0; s >>= 1) {
        if (tid < s) {
            smx[tid] = fmaxf(smx[tid], smx[tid + s]);
            smn[tid] = fminf(smn[tid], smn[tid + s]);
        }
        __syncthreads();
    }
    if (tid == 0) {
        atomicMax(&cal[0], __float_as_int(smx[0]));
        atomicMin(&cal[1], __float_as_int(smn[0]));
    }
}

// ---------------------------------------------------------------------------
// Combine: out[b] = (alpha*n2^2 + beta) * d2[b];  alpha/beta from 2 scalars.
// ---------------------------------------------------------------------------
__global__ __launch_bounds__(256)
void combine_kernel(const float* __restrict__ xparts, int nparts,
                    const int* __restrict__ cal,
                    const float* __restrict__ d2,
                    float* __restrict__ out, int B)
{
    const int b = blockIdx.x * blockDim.x + threadIdx.x;
    if (b >= B) return;
    const float mx = __int_as_float(cal[0]);
    const float mn = __int_as_float(cal[1]);
    const float alpha = (1.0f - 0.001f) / (mx - mn);
    const float beta  = 0.001f - alpha * mn;
    float n2 = 0.f;
    for (int y = 0; y < nparts; ++y) n2 += xparts[(size_t)y * B + b];
    out[b] = (alpha * n2 * n2 + beta) * d2[b];
}

// ---------------------------------------------------------------------------
// kernel_launch
// ---------------------------------------------------------------------------
extern "C" void kernel_launch(void* const* d_in, const int* in_sizes, int n_in,
                              void* d_out, int out_size)
{
    const float* x     = (const float*)d_in[0];
    const float* x_dot = (const float*)d_in[1];
    const float* pos   = (const float*)d_in[2];
    const float* W     = (const float*)d_in[3];
    float* out = (float*)d_out;

    const int D = (int)(sqrt((double)in_sizes[3]) + 0.5);
    const int B = in_sizes[0] / D;
    const int P = in_sizes[2] / D;
    const int NS = D / BN;   // 8 N-slices

    __half *xh, *ph, *wh;
    float *xparts, *pparts, *d2;
    int *cal;
    cudaGetSymbolAddress((void**)&xh, g_xh);
    cudaGetSymbolAddress((void**)&ph, g_ph);
    cudaGetSymbolAddress((void**)&wh, g_wh);
    cudaGetSymbolAddress((void**)&xparts, g_xparts);
    cudaGetSymbolAddress((void**)&pparts, g_pparts);
    cudaGetSymbolAddress((void**)&d2, g_d2);
    cudaGetSymbolAddress((void**)&cal, g_cal);

    cudaFuncSetAttribute(mma_gemm_norm,
                         cudaFuncAttributeMaxDynamicSharedMemorySize, SMEM_TOTAL);

    // unified prep: W transpose + fp16 converts + calib-cell init
    const int nWb = (D / 32) * (D / 32);
    const int nx4 = (B * D) / 4;
    const int np4 = (P * D) / 4;
    const int nCvtB = (nx4 + np4 + 255) / 256;
    prep_kernel<<<nWb + nCvtB, 256>>>(W, wh, D, nWb, x, xh, nx4, pos, ph, np4);

    // merged x-gemm + pos-gemm + x_dot row-norms (single launch)
    const int nxB = B / BM;          // 128
    const int npB = P / BM;          // 8
    const int ndB = B / (32 * NS);   // 128: each (fb, y) does 32 rows
    mma_gemm_norm<<<dim3(nxB + npB + ndB, NS), 256, SMEM_TOTAL>>>(
        xh, ph, wh, x_dot, D, nxB, npB, xparts, B, pparts, P, d2);

    // calibration (atomic max/min, deterministic)
    calib2_kernel<<<P / 256, 256>>>(pparts, P, NS, cal);

    // combine
    combine_kernel<<<(B + 255) / 256, 256>>>(xparts, NS, cal, d2, out, B);
}

// round 17
// speedup vs baseline: 1.0180x; 1.0180x over previous
#include <cuda_runtime.h>
#include <cuda_fp16.h>
#include <math.h>
#include <stdint.h>

// ===========================================================================
// ScoreMagnitudeMetric via warp-level mma.sync fp16 single-term GEMM:
//   scores = x @ W  ~=  fp16(x) @ fp16(W^T)   (fp32 accumulation)
//   n2[b] = ||scores_b||^2 ; out[b] = (alpha*n2^2 + beta) * ||x_dot_b||^2
// R17: exact revert to R15 (best known, 239.8us). R13 (4-stage), R14
// (2-N-tile), R16 (__ldcs + 2-row filler) all regressed -> R15 is the local
// optimum: gemm at the legacy mma.sync issue ceiling, prep at HBM floor.
// ===========================================================================

#define MAXB 32768
#define MAXP 2048
#define MAXD 1024

#define BM 256
#define BN 128
#define BK 64
#define NSLICE_MAX (MAXD / BN)   // 8

// scratch (device globals; no allocation allowed)
__device__ __half g_xh[(size_t)MAXB * MAXD];
__device__ __half g_ph[(size_t)MAXP * MAXD];
__device__ __half g_wh[(size_t)MAXD * MAXD];   // fp16(W^T)
__device__ float g_xparts[NSLICE_MAX * MAXB];
__device__ float g_pparts[NSLICE_MAX * MAXP];
__device__ float g_d2[MAXB];
__device__ int   g_cal[2];                     // [0]=max(n4) bits, [1]=min(n4) bits

// ---------------------------------------------------------------------------
// helpers
// ---------------------------------------------------------------------------
__device__ __forceinline__ uint32_t smem_to_u32(const void* p) {
    uint32_t a;
    asm("{ .reg .u64 t; cvta.to.shared.u64 t, %1; cvt.u32.u64 %0, t; }"
        : "=r"(a) : "l"(p));
    return a;
}

#define CP_ASYNC16(sm, g) \
    asm volatile("cp.async.cg.shared.global [%0], [%1], 16;" :: "r"(sm), "l"(g) : "memory")

// deferred arrival on mbar when all prior cp.async of this thread complete
#define CP_MBAR_ARRIVE(mbar) \
    asm volatile("cp.async.mbarrier.arrive.noinc.shared.b64 [%0];" \
                 :: "r"((uint32_t)(mbar)) : "memory")

#define MBARRIER_INIT(addr, cnt) \
    asm volatile("mbarrier.init.shared.b64 [%0], %1;" \
                 :: "r"((uint32_t)(addr)), "r"((uint32_t)(cnt)) : "memory")

#define MBARRIER_ARRIVE(addr) \
    asm volatile("mbarrier.arrive.shared.b64 _, [%0];" \
                 :: "r"((uint32_t)(addr)) : "memory")

#define MBARRIER_WAIT_PARITY(addr, par) do {                                   \
    uint32_t _m = (uint32_t)(addr); uint32_t _p = (uint32_t)(par); uint32_t _d;\
    asm volatile("{\n\t.reg .pred p;\n\t"                                      \
        "mbarrier.try_wait.parity.acquire.cta.shared::cta.b64 p, [%1], %2;\n\t"\
        "selp.b32 %0, 1, 0, p;\n\t}" : "=r"(_d) : "r"(_m), "r"(_p) : "memory");\
    if (!_d) {                                                                 \
        asm volatile("{\n\t.reg .pred P1;\n\t"                                 \
            "WL_%=:\n\t"                                                       \
            "mbarrier.try_wait.parity.acquire.cta.shared::cta.b64 P1, [%0], %1, 0x989680;\n\t" \
            "@P1 bra.uni WD_%=;\n\t"                                           \
            "bra.uni WL_%=;\n\t"                                               \
            "WD_%=:\n\t}" :: "r"(_m), "r"(_p) : "memory");                     \
    }                                                                          \
} while (0)

__device__ __forceinline__ void ldsm_x4(uint32_t* r, uint32_t addr) {
    asm volatile("ldmatrix.sync.aligned.m8n8.x4.shared.b16 {%0,%1,%2,%3}, [%4];"
                 : "=r"(r[0]), "=r"(r[1]), "=r"(r[2]), "=r"(r[3]) : "r"(addr));
}

__device__ __forceinline__ void mma16816(float* c, const uint32_t* a,
                                         uint32_t b0, uint32_t b1) {
    asm volatile(
        "mma.sync.aligned.m16n8k16.row.col.f32.f16.f16.f32 "
        "{%0,%1,%2,%3}, {%4,%5,%6,%7}, {%8,%9}, {%0,%1,%2,%3};"
        : "+f"(c[0]), "+f"(c[1]), "+f"(c[2]), "+f"(c[3])
        : "r"(a[0]), "r"(a[1]), "r"(a[2]), "r"(a[3]), "r"(b0), "r"(b1));
}

// ---------------------------------------------------------------------------
// Unified prep: grid sections on blockIdx.x
//   [0, nWb)       : W [k][j] -> Wt [j][k] fp16 (32x32 transpose tiles)
//   [nWb, ...)     : fp32 -> fp16 convert of x then pos (float4 lanes)
// Block 0 / thread 0 also re-initializes the calibration atomic cells.
// ---------------------------------------------------------------------------
__global__ __launch_bounds__(256)
void prep_kernel(const float* __restrict__ W, __half* __restrict__ wth, int D,
                 int nWb,
                 const float* __restrict__ x, __half* __restrict__ xh, int nx4,
                 const float* __restrict__ p, __half* __restrict__ ph, int np4)
{
    const int tid = threadIdx.x;
    const int bx  = blockIdx.x;

    if (bx < nWb) {
        if (bx == 0 && tid == 0) {
            g_cal[0] = 0;            // bits of 0.0f     (running max, n4 > 0)
            g_cal[1] = 0x7F7FFFFF;   // bits of FLT_MAX  (running min)
        }
        __shared__ float t[32][33];
        const int nJ = D / 32;
        const int j0 = (bx % nJ) * 32, k0 = (bx / nJ) * 32;
        const int tx = tid & 31, ty = tid >> 5;   // 32 x 8
        #pragma unroll
        for (int r = 0; r < 4; ++r)
            t[ty + 8 * r][tx] = W[(size_t)(k0 + ty + 8 * r) * D + j0 + tx];
        __syncthreads();
        #pragma unroll
        for (int r = 0; r < 4; ++r) {
            float v = t[tx][ty + 8 * r];
            wth[(size_t)(j0 + ty + 8 * r) * D + k0 + tx] = __float2half_rn(v);
        }
        return;
    }

    int i = (bx - nWb) * 256 + tid;
    const float* src;
    __half* dst;
    if (i < nx4) { src = x; dst = xh; }
    else         { src = p; dst = ph; i -= nx4; if (i >= np4) return; }
    float4 v = reinterpret_cast<const float4*>(src)[i];
    __half2* hp = reinterpret_cast<__half2*>(dst) + 2 * i;
    hp[0] = __half2(__float2half_rn(v.x), __float2half_rn(v.y));
    hp[1] = __half2(__float2half_rn(v.z), __float2half_rn(v.w));
}

// ---------------------------------------------------------------------------
// mma.sync GEMM-norm + fused x_dot row-norms. Grid sections on blockIdx.x:
//   [0, nxB)            : 256-row tiles of X  -> xparts
//   [nxB, nxB+npB)      : 256-row tiles of Pm -> pparts
//   [nxB+npB, +ndB)     : x_dot row sum-of-squares -> d2
//                         (each (fb, y) block handles a distinct 32-row strip
//                          -> no no-op blocks in the launch)
// GEMM block: 256 rows x 128 cols, 8 warps (4x2 of 64x64), 256 threads,
// 1 CTA/SM.  K in 64-chunks, 3-stage cp.async pipeline via mbarriers:
// FULL[s] (256 cp.async arrivals), CONS[s] (8 per-warp elected arrivals).
// Smem tile rows: 64 halves = 128 B data, 144 B stride (conflict-free ldsm).
// ---------------------------------------------------------------------------
#define A_TILE_B (256 * 144)                // 36864
#define B_TILE_B (128 * 144)                // 18432
#define A_OFF    0
#define B_OFF    (A_TILE_B)
#define STAGE_B  (A_TILE_B + B_TILE_B)      // 55296
#define NSTAGE   3
#define MBAR_OFF (NSTAGE * STAGE_B)         // 165888
#define SMEM_TOTAL (MBAR_OFF + 64)          // 165952

__global__ __launch_bounds__(256, 1)
void mma_gemm_norm(const __half* __restrict__ X,
                   const __half* __restrict__ Pm,
                   const __half* __restrict__ Wm,
                   const float* __restrict__ x_dot,
                   int D, int nxB, int npB,
                   float* __restrict__ xparts, int Brows,
                   float* __restrict__ pparts, int Prows,
                   float* __restrict__ d2)
{
    extern __shared__ __align__(128) char smem[];
    const uint32_t sm0 = smem_to_u32(smem);

    const int tid  = threadIdx.x;
    const int wid  = tid >> 5;
    const int lane = tid & 31;

    // ---- section 3: x_dot row-norms (DRAM-bound filler blocks) ----------
    // Each (fb, y) handles 32 rows: base = fb*256 + y*32; 4 rows per warp.
    if ((int)blockIdx.x >= nxB + npB) {
        const int fb = (int)blockIdx.x - nxB - npB;
        const int base = fb * 256 + (int)blockIdx.y * 32 + wid * 4;
        const int D4 = D >> 2;
        for (int r = 0; r < 4; ++r) {
            const float4* xd = reinterpret_cast<const float4*>(x_dot)
                             + (size_t)(base + r) * D4;
            float s = 0.f;
            for (int i = lane; i < D4; i += 32) {
                float4 v = xd[i];
                s += v.x * v.x + v.y * v.y + v.z * v.z + v.w * v.w;
            }
            #pragma unroll
            for (int off = 16; off > 0; off >>= 1)
                s += __shfl_down_sync(0xFFFFFFFFu, s, off);
            if (lane == 0) d2[base + r] = s;
        }
        return;
    }

    // ---- sections 1+2: GEMM-norm ----------------------------------------
    const int wm   = wid >> 1;          // 0..3 -> rows wm*64
    const int wn   = wid & 1;           // 0..1 -> cols wn*64
    const int KC   = D / BK;            // 16

    const bool isX = ((int)blockIdx.x < nxB);
    const int  mb  = isX ? (int)blockIdx.x : (int)blockIdx.x - nxB;
    const int  m0  = mb * BM;
    const int  n0  = blockIdx.y * BN;
    float* parts   = isX ? xparts : pparts;
    const int rowStride = isX ? Brows : Prows;

    const __half* gA = (isX ? X : Pm) + (size_t)m0 * D;
    const __half* gB = Wm + (size_t)n0 * D;

    const uint32_t FULL = sm0 + MBAR_OFF;        // 3 x 8B
    const uint32_t CONS = sm0 + MBAR_OFF + 24;   // 3 x 8B

    if (tid == 0) {
        #pragma unroll
        for (int s = 0; s < NSTAGE; ++s) {
            MBARRIER_INIT(FULL + 8 * s, 256);   // all threads' cp.async groups
            MBARRIER_INIT(CONS + 8 * s, 8);     // one elected lane per warp
        }
    }
    __syncthreads();

    float acc[4][8][4];
    #pragma unroll
    for (int i = 0; i < 4; ++i)
        #pragma unroll
        for (int j = 0; j < 8; ++j)
            #pragma unroll
            for (int c = 0; c < 4; ++c) acc[i][j][c] = 0.f;

    auto load_chunk = [&](int kc, int s) {
        const uint32_t sb = sm0 + (uint32_t)s * STAGE_B;
        const int kb = kc * BK;          // halves
        // A: 256 rows x 8 16B-segments = 2048 units; 8 per thread
        #pragma unroll
        for (int i = 0; i < 8; ++i) {
            int idx = tid + 256 * i;     // 0..2047
            int r = idx >> 3, c = idx & 7;
            uint32_t so = (uint32_t)(r * 144 + c * 16);
            CP_ASYNC16(sb + A_OFF + so, gA + (size_t)r * D + kb + c * 8);
        }
        // B: 128 rows x 8 segments = 1024 units; 4 per thread
        #pragma unroll
        for (int i = 0; i < 4; ++i) {
            int idx = tid + 256 * i;     // 0..1023
            int r = idx >> 3, c = idx & 7;
            uint32_t so = (uint32_t)(r * 144 + c * 16);
            CP_ASYNC16(sb + B_OFF + so, gB + (size_t)r * D + kb + c * 8);
        }
    };

    // ldmatrix per-lane address pieces (within-warp), hoisted
    const int a_row = (lane & 15);
    const int a_ku  = (lane >> 4);
    const int b_row = ((lane >> 4) << 3) + (lane & 7);
    const int b_ku  = ((lane >> 3) & 1);
    const int mrow  = wm * 64;
    const int nrow  = wn * 64;
    const uint32_t aBase0 = (uint32_t)((mrow + a_row) * 144 + a_ku * 16);
    const uint32_t bBase0 = (uint32_t)((nrow + b_row) * 144 + b_ku * 16);

    // prologue: chunks 0 and 1 in flight (deferred arrivals on FULL)
    load_chunk(0, 0);
    CP_MBAR_ARRIVE(FULL + 0);
    load_chunk(1, 1);
    CP_MBAR_ARRIVE(FULL + 8);

    for (int kc = 0; kc < KC; ++kc) {
        const int s = kc % NSTAGE;

        // produce chunk kc+2 into stage (kc+2)%3 (wait its previous reader)
        if (kc + 2 < KC) {
            const int s2 = (kc + 2) % NSTAGE;
            const uint32_t pc = (kc == 0) ? 1u : (uint32_t)(((kc - 1) / 3) & 1);
            MBARRIER_WAIT_PARITY(CONS + 8 * s2, pc);
            load_chunk(kc + 2, s2);
            CP_MBAR_ARRIVE(FULL + 8 * s2);
        }

        // consume chunk kc
        MBARRIER_WAIT_PARITY(FULL + 8 * s, (uint32_t)((kc / 3) & 1));

        const uint32_t sb = sm0 + (uint32_t)s * STAGE_B;
        const uint32_t aB = sb + A_OFF + aBase0;
        const uint32_t bB = sb + B_OFF + bBase0;
        #pragma unroll
        for (int ks = 0; ks < 4; ++ks) {        // four k16 steps per chunk
            const uint32_t kOff = (uint32_t)(ks * 32);
            uint32_t ah[4][4], bh[4][4];
            #pragma unroll
            for (int mt = 0; mt < 4; ++mt)
                ldsm_x4(ah[mt], aB + kOff + (uint32_t)(mt * 16 * 144));
            #pragma unroll
            for (int ng = 0; ng < 4; ++ng)
                ldsm_x4(bh[ng], bB + kOff + (uint32_t)(ng * 16 * 144));
            #pragma unroll
            for (int mt = 0; mt < 4; ++mt) {
                #pragma unroll
                for (int nt = 0; nt < 8; ++nt) {
                    uint32_t b0 = bh[nt >> 1][2 * (nt & 1)];
                    uint32_t b1 = bh[nt >> 1][2 * (nt & 1) + 1];
                    mma16816(acc[mt][nt], ah[mt], b0, b1);
                }
            }
        }

        // warp done reading stage s: one elected arrival per warp.
        if (lane == 0) MBARRIER_ARRIVE(CONS + 8 * s);
    }
    __syncthreads();   // all warps done (and all loads consumed) before reuse

    // ---- epilogue: row-wise sum of squares -------------------------------
    float* rbuf = reinterpret_cast<float*>(smem);   // [256][2]
    float rs0[4], rs1[4];
    #pragma unroll
    for (int mt = 0; mt < 4; ++mt) {
        float s0 = 0.f, s1 = 0.f;
        #pragma unroll
        for (int nt = 0; nt < 8; ++nt) {
            s0 += acc[mt][nt][0] * acc[mt][nt][0] + acc[mt][nt][1] * acc[mt][nt][1];
            s1 += acc[mt][nt][2] * acc[mt][nt][2] + acc[mt][nt][3] * acc[mt][nt][3];
        }
        s0 += __shfl_xor_sync(0xFFFFFFFFu, s0, 1);
        s0 += __shfl_xor_sync(0xFFFFFFFFu, s0, 2);
        s1 += __shfl_xor_sync(0xFFFFFFFFu, s1, 1);
        s1 += __shfl_xor_sync(0xFFFFFFFFu, s1, 2);
        rs0[mt] = s0;
        rs1[mt] = s1;
    }
    if ((lane & 3) == 0) {
        int rq = lane >> 2;
        #pragma unroll
        for (int mt = 0; mt < 4; ++mt) {
            int row = mrow + mt * 16 + rq;
            rbuf[row * 2 + wn] = rs0[mt];
            rbuf[(row + 8) * 2 + wn] = rs1[mt];
        }
    }
    __syncthreads();
    if (tid < BM) {
        float tot = rbuf[tid * 2 + 0] + rbuf[tid * 2 + 1];
        parts[(size_t)blockIdx.y * rowStride + m0 + tid] = tot;
    }
}

// ---------------------------------------------------------------------------
// Calibration: per-row n2 -> n4; block-reduce max/min; ONE atomicMax/Min per
// block on int-punned positive floats (deterministic).
// ---------------------------------------------------------------------------
__global__ __launch_bounds__(256)
void calib2_kernel(const float* __restrict__ pparts, int P, int nparts,
                   int* __restrict__ cal)
{
    __shared__ float smx[256], smn[256];
    const int tid = threadIdx.x;
    const int r = blockIdx.x * 256 + tid;

    float n4;
    {
        float n2 = 0.f;
        for (int y = 0; y < nparts; ++y) n2 += pparts[(size_t)y * P + r];
        n4 = n2 * n2;
    }
    smx[tid] = n4;
    smn[tid] = n4;
    __syncthreads();
    for (int s = 128; s > 0; s >>= 1) {
        if (tid < s) {
            smx[tid] = fmaxf(smx[tid], smx[tid + s]);
            smn[tid] = fminf(smn[tid], smn[tid + s]);
        }
        __syncthreads();
    }
    if (tid == 0) {
        atomicMax(&cal[0], __float_as_int(smx[0]));
        atomicMin(&cal[1], __float_as_int(smn[0]));
    }
}

// ---------------------------------------------------------------------------
// Combine: out[b] = (alpha*n2^2 + beta) * d2[b];  alpha/beta from 2 scalars.
// ---------------------------------------------------------------------------
__global__ __launch_bounds__(256)
void combine_kernel(const float* __restrict__ xparts, int nparts,
                    const int* __restrict__ cal,
                    const float* __restrict__ d2,
                    float* __restrict__ out, int B)
{
    const int b = blockIdx.x * blockDim.x + threadIdx.x;
    if (b >= B) return;
    const float mx = __int_as_float(cal[0]);
    const float mn = __int_as_float(cal[1]);
    const float alpha = (1.0f - 0.001f) / (mx - mn);
    const float beta  = 0.001f - alpha * mn;
    float n2 = 0.f;
    for (int y = 0; y < nparts; ++y) n2 += xparts[(size_t)y * B + b];
    out[b] = (alpha * n2 * n2 + beta) * d2[b];
}

// ---------------------------------------------------------------------------
// kernel_launch
// ---------------------------------------------------------------------------
extern "C" void kernel_launch(void* const* d_in, const int* in_sizes, int n_in,
                              void* d_out, int out_size)
{
    const float* x     = (const float*)d_in[0];
    const float* x_dot = (const float*)d_in[1];
    const float* pos   = (const float*)d_in[2];
    const float* W     = (const float*)d_in[3];
    float* out = (float*)d_out;

    const int D = (int)(sqrt((double)in_sizes[3]) + 0.5);
    const int B = in_sizes[0] / D;
    const int P = in_sizes[2] / D;
    const int NS = D / BN;   // 8 N-slices

    __half *xh, *ph, *wh;
    float *xparts, *pparts, *d2;
    int *cal;
    cudaGetSymbolAddress((void**)&xh, g_xh);
    cudaGetSymbolAddress((void**)&ph, g_ph);
    cudaGetSymbolAddress((void**)&wh, g_wh);
    cudaGetSymbolAddress((void**)&xparts, g_xparts);
    cudaGetSymbolAddress((void**)&pparts, g_pparts);
    cudaGetSymbolAddress((void**)&d2, g_d2);
    cudaGetSymbolAddress((void**)&cal, g_cal);

    cudaFuncSetAttribute(mma_gemm_norm,
                         cudaFuncAttributeMaxDynamicSharedMemorySize, SMEM_TOTAL);

    // unified prep: W transpose + fp16 converts + calib-cell init
    const int nWb = (D / 32) * (D / 32);
    const int nx4 = (B * D) / 4;
    const int np4 = (P * D) / 4;
    const int nCvtB = (nx4 + np4 + 255) / 256;
    prep_kernel<<<nWb + nCvtB, 256>>>(W, wh, D, nWb, x, xh, nx4, pos, ph, np4);

    // merged x-gemm + pos-gemm + x_dot row-norms (single launch)
    const int nxB = B / BM;          // 128
    const int npB = P / BM;          // 8
    const int ndB = B / (32 * NS);   // 128: each (fb, y) does 32 rows
    mma_gemm_norm<<<dim3(nxB + npB + ndB, NS), 256, SMEM_TOTAL>>>(
        xh, ph, wh, x_dot, D, nxB, npB, xparts, B, pparts, P, d2);

    // calibration (atomic max/min, deterministic)
    calib2_kernel<<<P / 256, 256>>>(pparts, P, NS, cal);

    // combine
    combine_kernel<<<(B + 255) / 256, 256>>>(xparts, NS, cal, d2, out, B);
}